// round 1
// baseline (speedup 1.0000x reference)
#include <cuda_runtime.h>

#define N_SEQ 2048
#define D_H   64
#define C_DIM 512
#define N_BH  16
#define SS_STRIDE 2052   // 2048 + 4 pad: breaks 32-bank aliasing between q-rows

// Scratch (device globals: no allocation allowed)
__device__ float g_Q[N_BH * N_SEQ * D_H];
__device__ float g_K[N_BH * N_SEQ * D_H];
__device__ float g_V[N_BH * N_SEQ * D_H];
__device__ float g_P[2 * N_SEQ * C_DIM];

// ---------------------------------------------------------------------------
// Y = X @ W^T + bias.  X:[M,512] row-major, W:[512,512] row-major.
// qkv_mode=1: scatter y[m,j] -> Y[((b*8+h)*2048+n)*64 + d]  (b=m>>11,n=m&2047,h=j>>6,d=j&63)
// qkv_mode=0: flat Y[m*512 + j]
// Tile 64x64, BK=16, 4x4 micro-tile, float4 shared reads (FMA-bound).
// ---------------------------------------------------------------------------
__global__ __launch_bounds__(256)
void gemm_bias_kernel(const float* __restrict__ X, const float* __restrict__ W,
                      const float* __restrict__ bias, float* __restrict__ Y,
                      int qkv_mode)
{
    __shared__ float sA[16 * 68];   // transposed: sA[c][m], pad 68
    __shared__ float sB[16 * 68];   // transposed: sB[c][j]

    const int tid = threadIdx.x;
    const int m0 = blockIdx.x * 64;
    const int j0 = blockIdx.y * 64;
    const int ty = tid >> 4;          // 0..15 (m micro-group)
    const int tx = tid & 15;          // 0..15 (j micro-group)
    const int lr = tid >> 2;          // 0..63 tile row for loads
    const int lc = (tid & 3) << 2;    // 0,4,8,12 col base

    float acc[4][4];
#pragma unroll
    for (int i = 0; i < 4; i++)
#pragma unroll
        for (int j = 0; j < 4; j++) acc[i][j] = 0.f;

    for (int kk = 0; kk < 512; kk += 16) {
        float4 av = *(const float4*)(X + (size_t)(m0 + lr) * 512 + kk + lc);
        float4 bv = *(const float4*)(W + (size_t)(j0 + lr) * 512 + kk + lc);
        sA[(lc + 0) * 68 + lr] = av.x; sA[(lc + 1) * 68 + lr] = av.y;
        sA[(lc + 2) * 68 + lr] = av.z; sA[(lc + 3) * 68 + lr] = av.w;
        sB[(lc + 0) * 68 + lr] = bv.x; sB[(lc + 1) * 68 + lr] = bv.y;
        sB[(lc + 2) * 68 + lr] = bv.z; sB[(lc + 3) * 68 + lr] = bv.w;
        __syncthreads();
#pragma unroll
        for (int c = 0; c < 16; ++c) {
            float4 a4 = *(const float4*)&sA[c * 68 + ty * 4];
            float4 b4 = *(const float4*)&sB[c * 68 + tx * 4];
            float a[4] = {a4.x, a4.y, a4.z, a4.w};
            float b[4] = {b4.x, b4.y, b4.z, b4.w};
#pragma unroll
            for (int i = 0; i < 4; i++)
#pragma unroll
                for (int j = 0; j < 4; j++)
                    acc[i][j] += a[i] * b[j];
        }
        __syncthreads();
    }

    float4 bb = *(const float4*)(bias + j0 + tx * 4);
#pragma unroll
    for (int i = 0; i < 4; i++) {
        const int m = m0 + ty * 4 + i;
        float4 r;
        r.x = acc[i][0] + bb.x; r.y = acc[i][1] + bb.y;
        r.z = acc[i][2] + bb.z; r.w = acc[i][3] + bb.w;
        if (qkv_mode) {
            const int b = m >> 11, n = m & 2047;
            const int h = j0 >> 6;
            *(float4*)(Y + ((size_t)(b * 8 + h) * 2048 + n) * 64 + tx * 4) = r;
        } else {
            *(float4*)(Y + (size_t)m * 512 + j0 + tx * 4) = r;
        }
    }
}

// ---------------------------------------------------------------------------
// Fused attention: per CTA = (bh, 16 q-rows).
//   Phase 1: S = Q Kt * 0.125  into shared (16 x 2048 fp32)
//   Phase 2: sparsemax per row (Newton on tau; exact fixed point of the
//            sort/cumsum formula), write attn to d_out
//   Phase 3: P = attn @ V  -> g_P in [B,N,C] layout
// ---------------------------------------------------------------------------
__global__ __launch_bounds__(256)
void attn_kernel(float* __restrict__ attn_out)
{
    extern __shared__ float sm[];
    float* sS = sm;                        // 16 * 2052
    float* sQ = sm + 16 * SS_STRIDE;       // 16 * 68
    float* sK = sQ + 16 * 68;              // 256 * 68 (K chunks, V chunks, red buf)

    const int tid = threadIdx.x;
    const int bh  = blockIdx.y;
    const int q0  = blockIdx.x * 16;

    // load Q tile (16 x 64)
    {
        const int q = tid >> 4, d4 = tid & 15;
        float4 v = *(const float4*)(g_Q + ((size_t)(bh * N_SEQ + q0 + q)) * 64 + d4 * 4);
        *(float4*)&sQ[q * 68 + d4 * 4] = v;
    }

    const int qg  = tid >> 6;   // 0..3 : q micro-group (4 rows)
    const int kg  = tid & 63;   // 0..63: k lane (k cols = kg + 64*j)
    const int ldr = tid >> 4;   // loader row base
    const int ldc = tid & 15;   // loader col (float4)

    // ---------------- Phase 1: scores ----------------
    for (int kc = 0; kc < 8; ++kc) {
        __syncthreads();  // protect sK reuse + sQ readiness on first iter
#pragma unroll
        for (int t = 0; t < 16; ++t) {
            const int r = ldr + t * 16;
            float4 v = *(const float4*)(g_K + ((size_t)(bh * N_SEQ + kc * 256 + r)) * 64 + ldc * 4);
            *(float4*)&sK[r * 68 + ldc * 4] = v;
        }
        __syncthreads();

        float acc[4][4];
#pragma unroll
        for (int i = 0; i < 4; i++)
#pragma unroll
            for (int j = 0; j < 4; j++) acc[i][j] = 0.f;

#pragma unroll 4
        for (int d4 = 0; d4 < 16; ++d4) {
            float4 a4[4], b4[4];
#pragma unroll
            for (int i = 0; i < 4; i++) a4[i] = *(const float4*)&sQ[(qg * 4 + i) * 68 + d4 * 4];
#pragma unroll
            for (int j = 0; j < 4; j++) b4[j] = *(const float4*)&sK[(kg + 64 * j) * 68 + d4 * 4];
#pragma unroll
            for (int i = 0; i < 4; i++)
#pragma unroll
                for (int j = 0; j < 4; j++)
                    acc[i][j] += a4[i].x * b4[j].x + a4[i].y * b4[j].y
                               + a4[i].z * b4[j].z + a4[i].w * b4[j].w;
        }
#pragma unroll
        for (int i = 0; i < 4; i++)
#pragma unroll
            for (int j = 0; j < 4; j++)
                sS[(qg * 4 + i) * SS_STRIDE + kc * 256 + kg + 64 * j] = acc[i][j] * 0.125f;
    }
    __syncthreads();

    // ---------------- Phase 2: sparsemax (one row per warp, twice) ----------------
    {
        const int warp = tid >> 5, lane = tid & 31;
#pragma unroll
        for (int rr = 0; rr < 2; ++rr) {
            const int q = warp + rr * 8;
            float* row = &sS[q * SS_STRIDE];

            float m = -3.402823466e38f;
            for (int t = 0; t < 64; ++t) m = fmaxf(m, row[lane + 32 * t]);
#pragma unroll
            for (int o = 16; o; o >>= 1) m = fmaxf(m, __shfl_xor_sync(0xffffffffu, m, o));

            // Newton on f(tau) = sum relu(s - tau) - 1, start tau = m-1 (f >= 0).
            // Convex piecewise-linear => monotone convergence to the exact
            // sparsemax threshold tau = (sum_support s - 1)/k.
            float tau = m - 1.0f;
            for (int it = 0; it < 64; ++it) {
                float S = 0.f; int cnt = 0;
                for (int t = 0; t < 64; ++t) {
                    float v = row[lane + 32 * t] - tau;
                    if (v > 0.f) { S += v; cnt++; }
                }
#pragma unroll
                for (int o = 16; o; o >>= 1) {
                    S   += __shfl_xor_sync(0xffffffffu, S, o);
                    cnt += __shfl_xor_sync(0xffffffffu, cnt, o);
                }
                if (cnt == 0) break;
                const float delta = (S - 1.0f) / (float)cnt;
                tau += delta;
                if (fabsf(delta) < 1e-8f) break;
            }

            for (int t = 0; t < 64; ++t) {
                const int k = lane + 32 * t;
                const float v = fmaxf(row[k] - tau, 0.f);
                row[k] = v;
                if (attn_out)
                    attn_out[((size_t)(bh * N_SEQ + q0 + q)) * N_SEQ + k] = v;
            }
        }
    }
    __syncthreads();

    // ---------------- Phase 3: P = attn @ V ----------------
    {
        const int ks  = tid >> 6;        // 0..3 : k-range split
        const int rem = tid & 63;
        const int qg3 = rem >> 4;        // 0..3 : q micro-group
        const int d4  = rem & 15;        // 0..15: output float4 column
        float4 acc4[4];
#pragma unroll
        for (int i = 0; i < 4; i++) acc4[i] = make_float4(0.f, 0.f, 0.f, 0.f);

        for (int kc = 0; kc < 8; ++kc) {
            __syncthreads();
#pragma unroll
            for (int t = 0; t < 16; ++t) {
                const int r = ldr + t * 16;
                float4 v = *(const float4*)(g_V + ((size_t)(bh * N_SEQ + kc * 256 + r)) * 64 + ldc * 4);
                *(float4*)&sK[r * 68 + ldc * 4] = v;
            }
            __syncthreads();
#pragma unroll 4
            for (int t = 0; t < 64; ++t) {
                const int k = ks * 64 + t;
                float4 v4 = *(const float4*)&sK[k * 68 + d4 * 4];
#pragma unroll
                for (int i = 0; i < 4; i++) {
                    const float a = sS[(qg3 * 4 + i) * SS_STRIDE + kc * 256 + k];
                    acc4[i].x += a * v4.x; acc4[i].y += a * v4.y;
                    acc4[i].z += a * v4.z; acc4[i].w += a * v4.w;
                }
            }
        }
        __syncthreads();
        float4* sRed = (float4*)sK;   // 4 * 16 * 16 float4 = 16 KB, fits in sK
#pragma unroll
        for (int i = 0; i < 4; i++)
            sRed[(ks * 16 + qg3 * 4 + i) * 16 + d4] = acc4[i];
        __syncthreads();
        {
            const int q = tid >> 4, dd = tid & 15;
            float4 r0 = sRed[(0 * 16 + q) * 16 + dd];
            float4 r1 = sRed[(1 * 16 + q) * 16 + dd];
            float4 r2 = sRed[(2 * 16 + q) * 16 + dd];
            float4 r3 = sRed[(3 * 16 + q) * 16 + dd];
            float4 r;
            r.x = (r0.x + r1.x) + (r2.x + r3.x);
            r.y = (r0.y + r1.y) + (r2.y + r3.y);
            r.z = (r0.z + r1.z) + (r2.z + r3.z);
            r.w = (r0.w + r1.w) + (r2.w + r3.w);
            const int b = bh >> 3, h = bh & 7;
            *(float4*)(g_P + ((size_t)(b * N_SEQ + q0 + q)) * C_DIM + h * 64 + dd * 4) = r;
        }
    }
}

// ---------------------------------------------------------------------------
extern "C" void kernel_launch(void* const* d_in, const int* in_sizes, int n_in,
                              void* d_out, int out_size)
{
    const float* x  = (const float*)d_in[0];
    const float* Wq = (const float*)d_in[1];
    const float* bq = (const float*)d_in[2];
    const float* Wk = (const float*)d_in[3];
    const float* bk = (const float*)d_in[4];
    const float* Wv = (const float*)d_in[5];
    const float* bv = (const float*)d_in[6];
    const float* Wo = (const float*)d_in[7];
    const float* bo = (const float*)d_in[8];

    float *dQ, *dK, *dV, *dP;
    cudaGetSymbolAddress((void**)&dQ, g_Q);
    cudaGetSymbolAddress((void**)&dK, g_K);
    cudaGetSymbolAddress((void**)&dV, g_V);
    cudaGetSymbolAddress((void**)&dP, g_P);

    float* out = (float*)d_out;
    const long long OUT_N = 2LL * N_SEQ * C_DIM;             // 2,097,152
    const long long ATT_N = (long long)N_BH * N_SEQ * N_SEQ; // 67,108,864
    float* final_ptr = nullptr;
    float* attn_ptr  = nullptr;
    if ((long long)out_size >= OUT_N + ATT_N) { final_ptr = out; attn_ptr = out + OUT_N; }
    else if ((long long)out_size >= ATT_N)    { attn_ptr = out; }
    else                                      { final_ptr = out; }

    dim3 gA(64, 8);
    gemm_bias_kernel<<<gA, 256>>>(x, Wq, bq, dQ, 1);
    gemm_bias_kernel<<<gA, 256>>>(x, Wk, bk, dK, 1);
    gemm_bias_kernel<<<gA, 256>>>(x, Wv, bv, dV, 1);

    const int smem = (16 * SS_STRIDE + 16 * 68 + 256 * 68) * 4;  // 205,312 B
    cudaFuncSetAttribute(attn_kernel, cudaFuncAttributeMaxDynamicSharedMemorySize, smem);
    attn_kernel<<<dim3(128, 16), 256, smem>>>(attn_ptr);

    if (final_ptr)
        gemm_bias_kernel<<<gA, 256>>>(dP, Wo, bo, final_ptr, 0);
}